// round 13
// baseline (speedup 1.0000x reference)
#include <cuda_runtime.h>
#include <cuda_bf16.h>
#include <math.h>
#include <stdint.h>

// Problem constants
#define BATCH   4
#define T_SEQ   4096
#define DMODEL  512
#define HDIM    128
#define M_ROWS  (BATCH * T_SEQ)   // 16384
#define NQT     (T_SEQ / 64)      // 64 q-tiles per batch
#define NSPLIT  4                 // KV-split ways
#define NJOBS   (BATCH * NQT * NSPLIT)

// pack two floats to bf16x2 word: lo 16 bits = first arg
__device__ __forceinline__ uint32_t packbf2(float lo, float hi) {
    uint32_t r;
    asm("cvt.rn.satfinite.bf16x2.f32 %0, %1, %2;" : "=r"(r) : "f"(hi), "f"(lo));
    return r;
}
__device__ __forceinline__ float bflo(uint32_t w) { return __uint_as_float(w << 16); }
__device__ __forceinline__ float bfhi(uint32_t w) { return __uint_as_float(w & 0xffff0000u); }
__device__ __forceinline__ float ex2(float x) {
    float y;
    asm("ex2.approx.f32 %0, %1;" : "=f"(y) : "f"(x));
    return y;
}

// ---------------- scratch (device globals: allocation-free) ----------------
__device__ __nv_bfloat16 g_xhi[M_ROWS * DMODEL];
__device__ __nv_bfloat16 g_xlo[M_ROWS * DMODEL];
__device__ __nv_bfloat16 g_wthi[3 * HDIM * DMODEL];   // W^T [y][n][k]
__device__ __nv_bfloat16 g_wtlo[3 * HDIM * DMODEL];
__device__ __nv_bfloat16 g_qhi[M_ROWS * HDIM];
__device__ __nv_bfloat16 g_qlo[M_ROWS * HDIM];
__device__ __nv_bfloat16 g_khi[M_ROWS * HDIM];
__device__ __nv_bfloat16 g_klo[M_ROWS * HDIM];
__device__ __nv_bfloat16 g_vhi[M_ROWS * HDIM];
__device__ __nv_bfloat16 g_vlo[M_ROWS * HDIM];
// KV-split partials (zero-initialized device globals; empty jobs rely on 0s in g_pO)
__device__ float g_pO[(size_t)NJOBS * 64 * HDIM];     // raw (unnormalized) O
__device__ float g_pm[NJOBS * 64];                    // log2-domain running max
__device__ float g_pl[NJOBS * 64];

// ---------------- mma / ldmatrix / cp.async helpers (base-target ISA) -------
__device__ __forceinline__ uint32_t smem_u32(const void* p) {
    uint32_t a;
    asm("{ .reg .u64 t; cvta.to.shared.u64 t, %1; cvt.u32.u64 %0, t; }" : "=r"(a) : "l"(p));
    return a;
}
__device__ __forceinline__ void mma_bf16(float* c, const uint32_t* a, uint32_t b0, uint32_t b1) {
    asm volatile(
        "mma.sync.aligned.m16n8k16.row.col.f32.bf16.bf16.f32 "
        "{%0,%1,%2,%3},{%4,%5,%6,%7},{%8,%9},{%0,%1,%2,%3};"
        : "+f"(c[0]), "+f"(c[1]), "+f"(c[2]), "+f"(c[3])
        : "r"(a[0]), "r"(a[1]), "r"(a[2]), "r"(a[3]), "r"(b0), "r"(b1));
}
__device__ __forceinline__ void ldmx4(uint32_t* r, uint32_t addr) {
    asm volatile("ldmatrix.sync.aligned.m8n8.x4.shared.b16 {%0,%1,%2,%3}, [%4];"
                 : "=r"(r[0]), "=r"(r[1]), "=r"(r[2]), "=r"(r[3]) : "r"(addr));
}
__device__ __forceinline__ void ldmx4t(uint32_t* r, uint32_t addr) {
    asm volatile("ldmatrix.sync.aligned.m8n8.x4.trans.shared.b16 {%0,%1,%2,%3}, [%4];"
                 : "=r"(r[0]), "=r"(r[1]), "=r"(r[2]), "=r"(r[3]) : "r"(addr));
}
__device__ __forceinline__ void cp16(uint32_t dst, const void* src) {
    asm volatile("cp.async.cg.shared.global [%0], [%1], 16;" :: "r"(dst), "l"(src) : "memory");
}
__device__ __forceinline__ void cp_commit() {
    asm volatile("cp.async.commit_group;" ::: "memory");
}
__device__ __forceinline__ void cp_wait0() {
    asm volatile("cp.async.wait_group 0;" ::: "memory");
}
__device__ __forceinline__ void cp_wait1() {
    asm volatile("cp.async.wait_group 1;" ::: "memory");
}
#define COPY4(d, s_) { (d)[0]=(s_)[0]; (d)[1]=(s_)[1]; (d)[2]=(s_)[2]; (d)[3]=(s_)[3]; }

// ============================================================================
// Prep 1: split x (fp32) -> bf16 hi/lo
// ============================================================================
__global__ __launch_bounds__(256) void split_x_kernel(const float* __restrict__ x)
{
    const int idx = blockIdx.x * 256 + threadIdx.x;     // float4 index
    float4 v = ((const float4*)x)[idx];
    uint32_t h0 = packbf2(v.x, v.y);
    uint32_t h1 = packbf2(v.z, v.w);
    float r0 = v.x - bflo(h0), r1 = v.y - bfhi(h0);
    float r2 = v.z - bflo(h1), r3 = v.w - bfhi(h1);
    *(uint2*)&g_xhi[(size_t)idx * 4] = make_uint2(h0, h1);
    *(uint2*)&g_xlo[(size_t)idx * 4] = make_uint2(packbf2(r0, r1), packbf2(r2, r3));
}

// ============================================================================
// Prep 2: transpose + split W [K=512][N=128] -> Wt [N][K] bf16 hi/lo, 3 mats
// ============================================================================
__global__ __launch_bounds__(256) void w_split_kernel(
    const float* __restrict__ wq, const float* __restrict__ wk, const float* __restrict__ wv)
{
    __shared__ float ts[32][33];
    const float* W = (blockIdx.z == 0) ? wq : (blockIdx.z == 1) ? wk : wv;
    const int k0 = blockIdx.x * 32;
    const int n0 = blockIdx.y * 32;
    const int txx = threadIdx.x & 31;
    const int tyy = threadIdx.x >> 5;   // 0..7
#pragma unroll
    for (int r = 0; r < 4; r++)
        ts[tyy + r * 8][txx] = W[(size_t)(k0 + tyy + r * 8) * HDIM + n0 + txx];
    __syncthreads();
#pragma unroll
    for (int r = 0; r < 4; r++) {
        int n = n0 + tyy + r * 8;
        int k = k0 + txx;
        float v = ts[txx][tyy + r * 8];
        __nv_bfloat16 hb = __float2bfloat16(v);
        float rr = v - __bfloat162float(hb);
        size_t o = (size_t)blockIdx.z * HDIM * DMODEL + (size_t)n * DMODEL + k;
        g_wthi[o] = hb;
        g_wtlo[o] = __float2bfloat16(rr);
    }
}

// ============================================================================
// QKV projection GEMM via HMMA split-bf16, 2-stage double buffer,
// depth-1 register prefetch of A/B fragments.
// BM=64, N=128 full, K=512 in chunks of 64; 128 thr (4 warps, 16 rows/warp).
// ============================================================================
#define XLD 72                                // smem row stride (bf16)
#define GX_B   (64  * XLD * 2)                //  9216 B per X tile
#define GW_B   (128 * XLD * 2)                // 18432 B per W tile
#define GSM_XH 0
#define GSM_XL (GSM_XH + GX_B)
#define GSM_WH (GSM_XL + GX_B)
#define GSM_WL (GSM_WH + GW_B)
#define GSTG   (GSM_WL + GW_B)                // 55296 B per stage
#define GSM_TOTAL (2 * GSTG)                  // 110592 B

__global__ __launch_bounds__(128, 2) void qkv_hmma_kernel(
    const float* __restrict__ bq, const float* __restrict__ bk, const float* __restrict__ bv)
{
    extern __shared__ char sg[];
    const uint32_t base = smem_u32(sg);

    const int tid  = threadIdx.x;
    const int w    = tid >> 5;
    const int lane = tid & 31;
    const int m0   = blockIdx.x * 64;
    const int y    = blockIdx.y;

    const __nv_bfloat16* wth = g_wthi + (size_t)y * HDIM * DMODEL;
    const __nv_bfloat16* wtl = g_wtlo + (size_t)y * HDIM * DMODEL;
    const float* bias = (y == 0) ? bq : (y == 1) ? bk : bv;

    float c[16][4];
#pragma unroll
    for (int j = 0; j < 16; j++)
#pragma unroll
        for (int q = 0; q < 4; q++) c[j][q] = 0.f;

    const int rowA  = 16 * w + (lane & 15);
    const int colA  = (lane >> 4) * 8;
    const int rowB4 = ((lane >> 4) << 3) + (lane & 7);   // x4: row within jn-pair
    const int colB4 = ((lane >> 3) & 1) * 8;

    auto issue = [&](int cidx, int stage) {
        const int k0 = cidx * 64;
        const uint32_t uXH = base + stage * GSTG + GSM_XH;
        const uint32_t uXL = base + stage * GSTG + GSM_XL;
        const uint32_t uWH = base + stage * GSTG + GSM_WH;
        const uint32_t uWL = base + stage * GSTG + GSM_WL;
#pragma unroll
        for (int it = 0; it < 4; it++) {
            int idx = tid + it * 128;
            int r = idx >> 3, cc = idx & 7;
            size_t go = (size_t)(m0 + r) * DMODEL + k0 + cc * 8;
            uint32_t so = (uint32_t)(r * XLD + cc * 8) * 2;
            cp16(uXH + so, g_xhi + go);
            cp16(uXL + so, g_xlo + go);
        }
#pragma unroll
        for (int it = 0; it < 8; it++) {
            int idx = tid + it * 128;
            int r = idx >> 3, cc = idx & 7;
            size_t go = (size_t)r * DMODEL + k0 + cc * 8;
            uint32_t so = (uint32_t)(r * XLD + cc * 8) * 2;
            cp16(uWH + so, wth + go);
            cp16(uWL + so, wtl + go);
        }
        cp_commit();
    };

    issue(0, 0);
    for (int cidx = 0; cidx < DMODEL / 64; cidx++) {
        const int stage = cidx & 1;
        if (cidx + 1 < DMODEL / 64) {
            issue(cidx + 1, stage ^ 1);
            cp_wait1();
        } else {
            cp_wait0();
        }
        __syncthreads();

        const uint32_t uXH = base + stage * GSTG + GSM_XH;
        const uint32_t uXL = base + stage * GSTG + GSM_XL;
        const uint32_t uWH = base + stage * GSTG + GSM_WH;
        const uint32_t uWL = base + stage * GSTG + GSM_WL;

        uint32_t ah[4], al[4], nah[4], nal[4];
        uint32_t bh[4], bl[4], nbh[4], nbl[4];
        {
            uint32_t aoff = (uint32_t)(rowA * XLD + colA) * 2;
            ldmx4(ah, uXH + aoff);
            ldmx4(al, uXL + aoff);
            uint32_t boff = (uint32_t)(rowB4 * XLD + colB4) * 2;
            ldmx4(bh, uWH + boff);
            ldmx4(bl, uWL + boff);
        }
#pragma unroll
        for (int kc = 0; kc < 4; kc++) {
            if (kc < 3) {
                uint32_t aoff = (uint32_t)(rowA * XLD + (kc + 1) * 16 + colA) * 2;
                ldmx4(nah, uXH + aoff);
                ldmx4(nal, uXL + aoff);
            }
#pragma unroll
            for (int jp = 0; jp < 8; jp++) {
                // prefetch next B fragments
                if (!(kc == 3 && jp == 7)) {
                    const int nkc = (jp < 7) ? kc : kc + 1;
                    const int njp = (jp < 7) ? jp + 1 : 0;
                    uint32_t off = (uint32_t)((16 * njp + rowB4) * XLD + nkc * 16 + colB4) * 2;
                    ldmx4(nbh, uWH + off);
                    ldmx4(nbl, uWL + off);
                }
                const int jn = 2 * jp;
                mma_bf16(c[jn],     ah, bh[0], bh[1]);
                mma_bf16(c[jn],     ah, bl[0], bl[1]);
                mma_bf16(c[jn],     al, bh[0], bh[1]);
                mma_bf16(c[jn + 1], ah, bh[2], bh[3]);
                mma_bf16(c[jn + 1], ah, bl[2], bl[3]);
                mma_bf16(c[jn + 1], al, bh[2], bh[3]);
                COPY4(bh, nbh);
                COPY4(bl, nbl);
            }
            COPY4(ah, nah);
            COPY4(al, nal);
        }
        __syncthreads();
    }

    // epilogue: Q scale folds 1/sqrt(128) AND log2(e) for exp2-domain softmax
    const float sc = (y == 0) ? 0.12753297f : 1.0f;
    __nv_bfloat16* hiA = (y == 0) ? g_qhi : (y == 1) ? g_khi : g_vhi;
    __nv_bfloat16* loA = (y == 0) ? g_qlo : (y == 1) ? g_klo : g_vlo;
    const int grp = lane >> 2;
    const int tic = lane & 3;
    const int r0 = m0 + 16 * w + grp;
    const int r1 = r0 + 8;

#pragma unroll
    for (int jn = 0; jn < 16; jn++) {
        int n = 8 * jn + 2 * tic;
        float2 bo = *(const float2*)(bias + n);
        float o0 = (c[jn][0] + bo.x) * sc;
        float o1 = (c[jn][1] + bo.y) * sc;
        float o2 = (c[jn][2] + bo.x) * sc;
        float o3 = (c[jn][3] + bo.y) * sc;
        uint32_t h0 = packbf2(o0, o1);
        uint32_t h1 = packbf2(o2, o3);
        *(uint32_t*)&hiA[(size_t)r0 * HDIM + n] = h0;
        *(uint32_t*)&hiA[(size_t)r1 * HDIM + n] = h1;
        *(uint32_t*)&loA[(size_t)r0 * HDIM + n] = packbf2(o0 - bflo(h0), o1 - bfhi(h0));
        *(uint32_t*)&loA[(size_t)r1 * HDIM + n] = packbf2(o2 - bflo(h1), o3 - bfhi(h1));
    }
}

// ============================================================================
// FA2-style flash attention (causal), split-bf16 HMMA, 4-way KV split,
// exp2-domain softmax, depth-1 register prefetch of all fragments.
// Block (qt, half): kt = half, half+4, ... <= qt.
// ============================================================================
#define LDT 136                         // smem row stride in bf16 (272B)
#define TILE_B (64 * LDT * 2)           // 17408 bytes per tile
#define ASM_QHI 0
#define ASM_QLO (ASM_QHI + TILE_B)
#define ASM_KHI (ASM_QLO + TILE_B)
#define ASM_KLO (ASM_KHI + TILE_B)
#define ASM_VHI (ASM_KLO + TILE_B)
#define ASM_VLO (ASM_VHI + TILE_B)
#define ASM_TOTAL (ASM_VLO + TILE_B)    // 104448 bytes

__global__ __launch_bounds__(128, 2) void attn_kernel()
{
    extern __shared__ char smem[];
    const uint32_t uQHI = smem_u32(smem) + ASM_QHI;
    const uint32_t uQLO = smem_u32(smem) + ASM_QLO;
    const uint32_t uKHI = smem_u32(smem) + ASM_KHI;
    const uint32_t uKLO = smem_u32(smem) + ASM_KLO;
    const uint32_t uVHI = smem_u32(smem) + ASM_VHI;
    const uint32_t uVLO = smem_u32(smem) + ASM_VLO;

    const int tid  = threadIdx.x;
    const int w    = tid >> 5;
    const int lane = tid & 31;
    const int b    = blockIdx.y;
    const int qt   = NQT - 1 - ((int)blockIdx.x >> 2);   // heavy jobs first
    const int half = (int)blockIdx.x & 3;
    const int q0   = qt * 64;

    const int grp  = lane >> 2;
    const int tic  = lane & 3;
    const int rl0  = 16 * w + grp;        // local row within tile
    const int rl1  = rl0 + 8;
    const int qr0  = q0 + rl0;
    const int qr1  = q0 + rl1;

    const size_t job = ((size_t)(b * NQT + qt) * NSPLIT + half);

    // empty job: record identity partial (g_pO slot stays zero-initialized)
    if (half > qt) {
        if (tic == 0) {
            g_pm[job * 64 + rl0] = -1e30f;
            g_pl[job * 64 + rl0] = 0.f;
            g_pm[job * 64 + rl1] = -1e30f;
            g_pl[job * 64 + rl1] = 0.f;
        }
        return;
    }

    const __nv_bfloat16* kh = g_khi + (size_t)b * T_SEQ * HDIM;
    const __nv_bfloat16* kl = g_klo + (size_t)b * T_SEQ * HDIM;
    const __nv_bfloat16* vh = g_vhi + (size_t)b * T_SEQ * HDIM;
    const __nv_bfloat16* vl = g_vlo + (size_t)b * T_SEQ * HDIM;

    auto issueK = [&](int kt_) {
        const int kb = kt_ * 64;
#pragma unroll
        for (int it = 0; it < 8; it++) {
            int idx = tid + it * 128;
            int r = idx >> 4, cc = idx & 15;
            size_t go = (size_t)(kb + r) * HDIM + cc * 8;
            uint32_t so = (uint32_t)(r * LDT + cc * 8) * 2;
            cp16(uKHI + so, kh + go);
            cp16(uKLO + so, kl + go);
        }
        cp_commit();
    };
    auto issueV = [&](int kt_) {
        const int kb = kt_ * 64;
#pragma unroll
        for (int it = 0; it < 8; it++) {
            int idx = tid + it * 128;
            int r = idx >> 4, cc = idx & 15;
            size_t go = (size_t)(kb + r) * HDIM + cc * 8;
            uint32_t so = (uint32_t)(r * LDT + cc * 8) * 2;
            cp16(uVHI + so, vh + go);
            cp16(uVLO + so, vl + go);
        }
        cp_commit();
    };

    float O[16][4];
#pragma unroll
    for (int j = 0; j < 16; j++)
#pragma unroll
        for (int q = 0; q < 4; q++) O[j][q] = 0.f;
    float m0 = -1e30f, m1 = -1e30f, l0 = 0.f, l1 = 0.f;

    const int rowA  = 16 * w + (lane & 15);
    const int colA  = (lane >> 4) * 8;
    const int rowK4 = ((lane >> 4) << 3) + (lane & 7);   // x4 non-trans (j-pair)
    const int colK4 = ((lane >> 3) & 1) * 8;
    const int rowV4 = lane & 15;                         // x4 trans (jn-pair)
    const int colV4 = ((lane >> 4) & 1) * 8;

    // ---- stage Q tile hi/lo into smem (persists) + preload K,V ----
    {
        const __nv_bfloat16* qh = g_qhi + ((size_t)b * T_SEQ + q0) * HDIM;
        const __nv_bfloat16* ql = g_qlo + ((size_t)b * T_SEQ + q0) * HDIM;
#pragma unroll
        for (int it = 0; it < 8; it++) {
            int idx = tid + it * 128;
            int r = idx >> 4, cc = idx & 15;
            uint32_t so = (uint32_t)(r * LDT + cc * 8) * 2;
            cp16(uQHI + so, qh + (size_t)r * HDIM + cc * 8);
            cp16(uQLO + so, ql + (size_t)r * HDIM + cc * 8);
        }
        cp_commit();
    }
    const int kt0 = half;
    issueK(kt0);
    issueV(kt0);
    cp_wait0();
    __syncthreads();

    for (int kt = kt0; kt <= qt; kt += NSPLIT) {
        const bool has_next = (kt + NSPLIT <= qt);
        const int kb = kt * 64;

        // ---- S = Q K^T (split chain, register-prefetched fragments) ----
        float s[8][4];
#pragma unroll
        for (int j = 0; j < 8; j++)
#pragma unroll
            for (int q = 0; q < 4; q++) s[j][q] = 0.f;

        {
            uint32_t ah[4], al[4], nah[4], nal[4];
            uint32_t bh[4], bl[4], nbh[4], nbl[4];
            {
                uint32_t aoff = (uint32_t)(rowA * LDT + colA) * 2;
                ldmx4(ah, uQHI + aoff);
                ldmx4(al, uQLO + aoff);
                uint32_t boff = (uint32_t)(rowK4 * LDT + colK4) * 2;
                ldmx4(bh, uKHI + boff);
                ldmx4(bl, uKLO + boff);
            }
#pragma unroll
            for (int kc = 0; kc < 8; kc++) {
                if (kc < 7) {
                    uint32_t aoff = (uint32_t)(rowA * LDT + (kc + 1) * 16 + colA) * 2;
                    ldmx4(nah, uQHI + aoff);
                    ldmx4(nal, uQLO + aoff);
                }
#pragma unroll
                for (int jp = 0; jp < 4; jp++) {
                    if (!(kc == 7 && jp == 3)) {
                        const int nkc = (jp < 3) ? kc : kc + 1;
                        const int njp = (jp < 3) ? jp + 1 : 0;
                        uint32_t off = (uint32_t)((16 * njp + rowK4) * LDT + nkc * 16 + colK4) * 2;
                        ldmx4(nbh, uKHI + off);
                        ldmx4(nbl, uKLO + off);
                    }
                    const int j = 2 * jp;
                    mma_bf16(s[j],     ah, bh[0], bh[1]);
                    mma_bf16(s[j],     ah, bl[0], bl[1]);
                    mma_bf16(s[j],     al, bh[0], bh[1]);
                    mma_bf16(s[j + 1], ah, bh[2], bh[3]);
                    mma_bf16(s[j + 1], ah, bl[2], bl[3]);
                    mma_bf16(s[j + 1], al, bh[2], bh[3]);
                    COPY4(bh, nbh);
                    COPY4(bl, nbl);
                }
                COPY4(ah, nah);
                COPY4(al, nal);
            }
        }
        __syncthreads();                      // done reading K bufs
        if (has_next) issueK(kt + NSPLIT);    // K prefetch flies during softmax+PV

        // ---- causal mask (diag tile only) ----
        if (kt == qt) {
            const int cb = kb + 2 * tic;
#pragma unroll
            for (int j = 0; j < 8; j++) {
                int c0 = cb + 8 * j, c1 = c0 + 1;
                if (c0 > qr0) s[j][0] = -1e30f;
                if (c1 > qr0) s[j][1] = -1e30f;
                if (c0 > qr1) s[j][2] = -1e30f;
                if (c1 > qr1) s[j][3] = -1e30f;
            }
        }

        // ---- online softmax (exp2 domain) ----
        float mx0 = -1e30f, mx1 = -1e30f;
#pragma unroll
        for (int j = 0; j < 8; j++) {
            mx0 = fmaxf(mx0, fmaxf(s[j][0], s[j][1]));
            mx1 = fmaxf(mx1, fmaxf(s[j][2], s[j][3]));
        }
        mx0 = fmaxf(mx0, __shfl_xor_sync(0xffffffffu, mx0, 1));
        mx0 = fmaxf(mx0, __shfl_xor_sync(0xffffffffu, mx0, 2));
        mx1 = fmaxf(mx1, __shfl_xor_sync(0xffffffffu, mx1, 1));
        mx1 = fmaxf(mx1, __shfl_xor_sync(0xffffffffu, mx1, 2));
        const float mn0 = fmaxf(m0, mx0);
        const float mn1 = fmaxf(m1, mx1);
        const float al0 = ex2(m0 - mn0);
        const float al1 = ex2(m1 - mn1);
        m0 = mn0; m1 = mn1;

        uint32_t phi[8][2], plo[8][2];
        float la0 = 0.f, la1 = 0.f;
#pragma unroll
        for (int j = 0; j < 8; j++) {
            float p0 = ex2(s[j][0] - mn0);
            float p1 = ex2(s[j][1] - mn0);
            float p2 = ex2(s[j][2] - mn1);
            float p3 = ex2(s[j][3] - mn1);
            la0 += p0 + p1; la1 += p2 + p3;
            uint32_t h0 = packbf2(p0, p1);
            uint32_t h1 = packbf2(p2, p3);
            phi[j][0] = h0; phi[j][1] = h1;
            plo[j][0] = packbf2(p0 - bflo(h0), p1 - bfhi(h0));
            plo[j][1] = packbf2(p2 - bflo(h1), p3 - bfhi(h1));
        }
        la0 += __shfl_xor_sync(0xffffffffu, la0, 1);
        la0 += __shfl_xor_sync(0xffffffffu, la0, 2);
        la1 += __shfl_xor_sync(0xffffffffu, la1, 1);
        la1 += __shfl_xor_sync(0xffffffffu, la1, 2);
        l0 = l0 * al0 + la0;
        l1 = l1 * al1 + la1;

        // skip O rescale when entire warp's alphas are exactly 1
        if (!__all_sync(0xffffffffu, (al0 == 1.f) & (al1 == 1.f))) {
#pragma unroll
            for (int j = 0; j < 16; j++) {
                O[j][0] *= al0; O[j][1] *= al0;
                O[j][2] *= al1; O[j][3] *= al1;
            }
        }

        // V(kt) must be resident: for kt>kt0 its group may still fly
        if (kt > kt0) {
            if (has_next) cp_wait1(); else cp_wait0();
            __syncthreads();
        }

        // ---- O += P V (split chain, register-prefetched V fragments) ----
        {
            uint32_t vhf[4], vlf[4], nvh[4], nvl[4];
            {
                uint32_t off = (uint32_t)(rowV4 * LDT + colV4) * 2;
                ldmx4t(vhf, uVHI + off);
                ldmx4t(vlf, uVLO + off);
            }
#pragma unroll
            for (int kc = 0; kc < 4; kc++) {
                uint32_t ah[4] = { phi[2*kc][0], phi[2*kc][1], phi[2*kc+1][0], phi[2*kc+1][1] };
                uint32_t al[4] = { plo[2*kc][0], plo[2*kc][1], plo[2*kc+1][0], plo[2*kc+1][1] };
#pragma unroll
                for (int jnp = 0; jnp < 8; jnp++) {
                    if (!(kc == 3 && jnp == 7)) {
                        const int nkc = (jnp < 7) ? kc : kc + 1;
                        const int njn = (jnp < 7) ? jnp + 1 : 0;
                        uint32_t off = (uint32_t)((16 * nkc + rowV4) * LDT + colV4 + 16 * njn * LDT) * 2;
                        // note: jn advance moves along n (columns of V) = +16*njn bf16 in row
                        off = (uint32_t)((16 * nkc + rowV4) * LDT + colV4) * 2 + (uint32_t)(16 * njn) * 2;
                        ldmx4t(nvh, uVHI + off);
                        ldmx4t(nvl, uVLO + off);
                    }
                    const int jn = 2 * jnp;
                    mma_bf16(O[jn],     ah, vhf[0], vhf[1]);
                    mma_bf16(O[jn],     ah, vlf[0], vlf[1]);
                    mma_bf16(O[jn],     al, vhf[0], vhf[1]);
                    mma_bf16(O[jn + 1], ah, vhf[2], vhf[3]);
                    mma_bf16(O[jn + 1], ah, vlf[2], vlf[3]);
                    mma_bf16(O[jn + 1], al, vhf[2], vhf[3]);
                    COPY4(vhf, nvh);
                    COPY4(vlf, nvl);
                }
            }
        }
        __syncthreads();                      // done reading V bufs
        if (has_next) {
            issueV(kt + NSPLIT);              // V prefetch flies during next S
            cp_wait1();                       // K(kt+NSPLIT) resident (V still flying)
            __syncthreads();
        }
    }

    // ---- epilogue: write raw partial (O, m, l) ----
    float* pO = g_pO + job * 64 * HDIM;
    if (tic == 0) {
        g_pm[job * 64 + rl0] = m0;
        g_pl[job * 64 + rl0] = l0;
        g_pm[job * 64 + rl1] = m1;
        g_pl[job * 64 + rl1] = l1;
    }
#pragma unroll
    for (int jn = 0; jn < 16; jn++) {
        int col = 8 * jn + 2 * tic;
        *(float2*)(pO + (size_t)rl0 * HDIM + col) = make_float2(O[jn][0], O[jn][1]);
        *(float2*)(pO + (size_t)rl1 * HDIM + col) = make_float2(O[jn][2], O[jn][3]);
    }
}

// ============================================================================
// Merge: combine the NSPLIT KV-split partials per q-row (exp2 domain).
// grid (NQT, BATCH), 256 threads: row = tid>>2 (64 rows), 32 cols/thread.
// ============================================================================
__global__ __launch_bounds__(256) void merge_kernel(float* __restrict__ out)
{
    const int qt = blockIdx.x;
    const int b  = blockIdx.y;
    const int r  = threadIdx.x >> 2;         // 0..63
    const int cq = threadIdx.x & 3;          // col quarter
    const size_t j0 = ((size_t)(b * NQT + qt) * NSPLIT);

    float mM = -1e30f;
    float mv[NSPLIT], lv[NSPLIT];
#pragma unroll
    for (int i = 0; i < NSPLIT; i++) {
        mv[i] = g_pm[(j0 + i) * 64 + r];
        lv[i] = g_pl[(j0 + i) * 64 + r];
        mM = fmaxf(mM, mv[i]);
    }
    float a[NSPLIT], den = 0.f;
#pragma unroll
    for (int i = 0; i < NSPLIT; i++) {
        a[i] = ex2(mv[i] - mM);
        den += a[i] * lv[i];
    }
    const float inv = 1.f / den;

    float* orow = out + ((size_t)b * T_SEQ + qt * 64 + r) * HDIM + cq * 32;
#pragma unroll
    for (int c4 = 0; c4 < 8; c4++) {
        float4 acc = make_float4(0.f, 0.f, 0.f, 0.f);
#pragma unroll
        for (int i = 0; i < NSPLIT; i++) {
            const float* p = g_pO + (j0 + i) * 64 * HDIM + (size_t)r * HDIM + cq * 32 + c4 * 4;
            float4 v = *(const float4*)p;
            acc.x += a[i] * v.x;
            acc.y += a[i] * v.y;
            acc.z += a[i] * v.z;
            acc.w += a[i] * v.w;
        }
        acc.x *= inv; acc.y *= inv; acc.z *= inv; acc.w *= inv;
        *(float4*)(orow + c4 * 4) = acc;
    }
}

// ============================================================================
// launch
// ============================================================================
extern "C" void kernel_launch(void* const* d_in, const int* in_sizes, int n_in,
                              void* d_out, int out_size)
{
    (void)in_sizes; (void)n_in; (void)out_size;
    const float* x  = (const float*)d_in[0];
    // d_in[1] = mask (int32 causal tril) -- causality applied analytically
    const float* wq = (const float*)d_in[2];
    const float* bq = (const float*)d_in[3];
    const float* wk = (const float*)d_in[4];
    const float* bk = (const float*)d_in[5];
    const float* wv = (const float*)d_in[6];
    const float* bv = (const float*)d_in[7];
    float* out = (float*)d_out;

    split_x_kernel<<<M_ROWS * DMODEL / 4 / 256, 256>>>(x);

    dim3 gw(DMODEL / 32, HDIM / 32, 3);
    w_split_kernel<<<gw, 256>>>(wq, wk, wv);

    cudaFuncSetAttribute(qkv_hmma_kernel, cudaFuncAttributeMaxDynamicSharedMemorySize, GSM_TOTAL);
    dim3 gg(M_ROWS / 64, 3);
    qkv_hmma_kernel<<<gg, 128, GSM_TOTAL>>>(bq, bk, bv);

    cudaFuncSetAttribute(attn_kernel, cudaFuncAttributeMaxDynamicSharedMemorySize, ASM_TOTAL);
    dim3 ga(NSPLIT * NQT, BATCH);
    attn_kernel<<<ga, 128, ASM_TOTAL>>>();

    dim3 gm(NQT, BATCH);
    merge_kernel<<<gm, 256>>>(out);
}

// round 14
// speedup vs baseline: 1.0497x; 1.0497x over previous
#include <cuda_runtime.h>
#include <cuda_bf16.h>
#include <math.h>
#include <stdint.h>

// Problem constants
#define BATCH   4
#define T_SEQ   4096
#define DMODEL  512
#define HDIM    128
#define M_ROWS  (BATCH * T_SEQ)   // 16384
#define NQT     (T_SEQ / 64)      // 64 q-tiles per batch
#define NSPLIT  4                 // KV-split ways
#define NJOBS   (BATCH * NQT * NSPLIT)

// pack two floats to bf16x2 word: lo 16 bits = first arg
__device__ __forceinline__ uint32_t packbf2(float lo, float hi) {
    uint32_t r;
    asm("cvt.rn.satfinite.bf16x2.f32 %0, %1, %2;" : "=r"(r) : "f"(hi), "f"(lo));
    return r;
}
__device__ __forceinline__ float bflo(uint32_t w) { return __uint_as_float(w << 16); }
__device__ __forceinline__ float bfhi(uint32_t w) { return __uint_as_float(w & 0xffff0000u); }
__device__ __forceinline__ float ex2(float x) {
    float y;
    asm("ex2.approx.f32 %0, %1;" : "=f"(y) : "f"(x));
    return y;
}

// ---------------- scratch (device globals: allocation-free) ----------------
__device__ __nv_bfloat16 g_wthi[3 * HDIM * DMODEL];   // W^T [y][n][k]
__device__ __nv_bfloat16 g_wtlo[3 * HDIM * DMODEL];
__device__ __nv_bfloat16 g_qhi[M_ROWS * HDIM];
__device__ __nv_bfloat16 g_qlo[M_ROWS * HDIM];
__device__ __nv_bfloat16 g_khi[M_ROWS * HDIM];
__device__ __nv_bfloat16 g_klo[M_ROWS * HDIM];
__device__ __nv_bfloat16 g_vhi[M_ROWS * HDIM];
__device__ __nv_bfloat16 g_vlo[M_ROWS * HDIM];
// KV-split partials (zero-initialized device globals; empty jobs rely on 0s in g_pO)
__device__ float g_pO[(size_t)NJOBS * 64 * HDIM];     // raw (unnormalized) O
__device__ float g_pm[NJOBS * 64];                    // log2-domain running max
__device__ float g_pl[NJOBS * 64];

// ---------------- mma / ldmatrix / cp.async helpers (base-target ISA) -------
__device__ __forceinline__ uint32_t smem_u32(const void* p) {
    uint32_t a;
    asm("{ .reg .u64 t; cvta.to.shared.u64 t, %1; cvt.u32.u64 %0, t; }" : "=r"(a) : "l"(p));
    return a;
}
__device__ __forceinline__ void mma_bf16(float* c, const uint32_t* a, uint32_t b0, uint32_t b1) {
    asm volatile(
        "mma.sync.aligned.m16n8k16.row.col.f32.bf16.bf16.f32 "
        "{%0,%1,%2,%3},{%4,%5,%6,%7},{%8,%9},{%0,%1,%2,%3};"
        : "+f"(c[0]), "+f"(c[1]), "+f"(c[2]), "+f"(c[3])
        : "r"(a[0]), "r"(a[1]), "r"(a[2]), "r"(a[3]), "r"(b0), "r"(b1));
}
__device__ __forceinline__ void ldmx4(uint32_t* r, uint32_t addr) {
    asm volatile("ldmatrix.sync.aligned.m8n8.x4.shared.b16 {%0,%1,%2,%3}, [%4];"
                 : "=r"(r[0]), "=r"(r[1]), "=r"(r[2]), "=r"(r[3]) : "r"(addr));
}
__device__ __forceinline__ void ldmx4t(uint32_t* r, uint32_t addr) {
    asm volatile("ldmatrix.sync.aligned.m8n8.x4.trans.shared.b16 {%0,%1,%2,%3}, [%4];"
                 : "=r"(r[0]), "=r"(r[1]), "=r"(r[2]), "=r"(r[3]) : "r"(addr));
}
__device__ __forceinline__ void cp16(uint32_t dst, const void* src) {
    asm volatile("cp.async.cg.shared.global [%0], [%1], 16;" :: "r"(dst), "l"(src) : "memory");
}
__device__ __forceinline__ void cp_commit() {
    asm volatile("cp.async.commit_group;" ::: "memory");
}
__device__ __forceinline__ void cp_wait0() {
    asm volatile("cp.async.wait_group 0;" ::: "memory");
}
__device__ __forceinline__ void cp_wait1() {
    asm volatile("cp.async.wait_group 1;" ::: "memory");
}

// ============================================================================
// Prep: transpose + split W [K=512][N=128] -> Wt [N][K] bf16 hi/lo, 3 mats
// ============================================================================
__global__ __launch_bounds__(256) void w_split_kernel(
    const float* __restrict__ wq, const float* __restrict__ wk, const float* __restrict__ wv)
{
    __shared__ float ts[32][33];
    const float* W = (blockIdx.z == 0) ? wq : (blockIdx.z == 1) ? wk : wv;
    const int k0 = blockIdx.x * 32;
    const int n0 = blockIdx.y * 32;
    const int txx = threadIdx.x & 31;
    const int tyy = threadIdx.x >> 5;   // 0..7
#pragma unroll
    for (int r = 0; r < 4; r++)
        ts[tyy + r * 8][txx] = W[(size_t)(k0 + tyy + r * 8) * HDIM + n0 + txx];
    __syncthreads();
#pragma unroll
    for (int r = 0; r < 4; r++) {
        int n = n0 + tyy + r * 8;
        int k = k0 + txx;
        float v = ts[txx][tyy + r * 8];
        __nv_bfloat16 hb = __float2bfloat16(v);
        float rr = v - __bfloat162float(hb);
        size_t o = (size_t)blockIdx.z * HDIM * DMODEL + (size_t)n * DMODEL + k;
        g_wthi[o] = hb;
        g_wtlo[o] = __float2bfloat16(rr);
    }
}

// ============================================================================
// QKV projection GEMM via HMMA split-bf16, 2-stage double buffer.
// X loaded fp32 via LDG one chunk ahead, split to bf16 hi/lo in-register,
// STS'd into the staging buffers (split_x kernel fused away).
// BM=64, N=128 full, K=512 in chunks of 64; 128 thr (4 warps, 16 rows/warp).
// ============================================================================
#define XLD 72                                // smem row stride (bf16)
#define GX_B   (64  * XLD * 2)                //  9216 B per X tile
#define GW_B   (128 * XLD * 2)                // 18432 B per W tile
#define GSM_XH 0
#define GSM_XL (GSM_XH + GX_B)
#define GSM_WH (GSM_XL + GX_B)
#define GSM_WL (GSM_WH + GW_B)
#define GSTG   (GSM_WL + GW_B)                // 55296 B per stage
#define GSM_TOTAL (2 * GSTG)                  // 110592 B
#define NCHUNK (DMODEL / 64)                  // 8

__global__ __launch_bounds__(128, 2) void qkv_hmma_kernel(
    const float* __restrict__ x,
    const float* __restrict__ bq, const float* __restrict__ bk, const float* __restrict__ bv)
{
    extern __shared__ char sg[];
    const uint32_t base = smem_u32(sg);

    const int tid  = threadIdx.x;
    const int w    = tid >> 5;
    const int lane = tid & 31;
    const int m0   = blockIdx.x * 64;
    const int y    = blockIdx.y;

    const __nv_bfloat16* wth = g_wthi + (size_t)y * HDIM * DMODEL;
    const __nv_bfloat16* wtl = g_wtlo + (size_t)y * HDIM * DMODEL;
    const float* bias = (y == 0) ? bq : (y == 1) ? bk : bv;

    float c[16][4];
#pragma unroll
    for (int j = 0; j < 16; j++)
#pragma unroll
        for (int q = 0; q < 4; q++) c[j][q] = 0.f;

    const int rowA  = 16 * w + (lane & 15);
    const int colA  = (lane >> 4) * 8;
    const int rowB4 = ((lane >> 4) << 3) + (lane & 7);   // x4: row within jn-pair
    const int colB4 = ((lane >> 3) & 1) * 8;

    // per-thread X staging: 32 fp32 (4 rows x 8 cols) per chunk
    // thread covers rows xr..xr+? : 128 thr * 8 float4 loads; layout:
    // float4 idx f in 0..7: row = (tid>>3)*4 + (f>>1), col4 = (tid&7)*... simpler:
    // X chunk = 64 rows x 64 cols; per thread: 8 float4 = idx = tid + it*128
    //   (it 0..7): r = idx>>4 (0..63), c4 = idx&15 (0..15) -> col = c4*4
    float4 xr[8];

    auto ldgX = [&](int cidx) {
        const int k0 = cidx * 64;
#pragma unroll
        for (int it = 0; it < 8; it++) {
            int idx = tid + it * 128;
            int r = idx >> 4, c4 = idx & 15;
            xr[it] = *(const float4*)(x + (size_t)(m0 + r) * DMODEL + k0 + c4 * 4);
        }
    };
    auto stsX = [&](int stage) {
        const uint32_t uXH = base + stage * GSTG + GSM_XH;
        const uint32_t uXL = base + stage * GSTG + GSM_XL;
#pragma unroll
        for (int it = 0; it < 8; it++) {
            int idx = tid + it * 128;
            int r = idx >> 4, c4 = idx & 15;
            float4 v = xr[it];
            uint32_t h0 = packbf2(v.x, v.y);
            uint32_t h1 = packbf2(v.z, v.w);
            uint32_t l0 = packbf2(v.x - bflo(h0), v.y - bfhi(h0));
            uint32_t l1 = packbf2(v.z - bflo(h1), v.w - bfhi(h1));
            uint32_t so = (uint32_t)(r * XLD + c4 * 4) * 2;
            *(uint2*)(sg + (stage * GSTG + GSM_XH) + so) = make_uint2(h0, h1);
            *(uint2*)(sg + (stage * GSTG + GSM_XL) + so) = make_uint2(l0, l1);
        }
        (void)uXH; (void)uXL;
    };
    auto issueW = [&](int cidx, int stage) {
        const int k0 = cidx * 64;
        const uint32_t uWH = base + stage * GSTG + GSM_WH;
        const uint32_t uWL = base + stage * GSTG + GSM_WL;
#pragma unroll
        for (int it = 0; it < 8; it++) {
            int idx = tid + it * 128;
            int r = idx >> 3, cc = idx & 7;
            size_t go = (size_t)r * DMODEL + k0 + cc * 8;
            uint32_t so = (uint32_t)(r * XLD + cc * 8) * 2;
            cp16(uWH + so, wth + go);
            cp16(uWL + so, wtl + go);
        }
        cp_commit();
    };

    // prologue: W(0) via cp.async, X(0) via LDG
    issueW(0, 0);
    ldgX(0);

    for (int cidx = 0; cidx < NCHUNK; cidx++) {
        const int stage = cidx & 1;
        const bool has_next = (cidx + 1 < NCHUNK);
        if (has_next) issueW(cidx + 1, stage ^ 1);
        stsX(stage);                       // convert + store current X chunk
        if (has_next) ldgX(cidx + 1);      // prefetch next X into regs
        if (has_next) cp_wait1(); else cp_wait0();   // W(cidx) resident
        __syncthreads();

        const uint32_t uXH = base + stage * GSTG + GSM_XH;
        const uint32_t uXL = base + stage * GSTG + GSM_XL;
        const uint32_t uWH = base + stage * GSTG + GSM_WH;
        const uint32_t uWL = base + stage * GSTG + GSM_WL;
#pragma unroll
        for (int kc = 0; kc < 4; kc++) {
            uint32_t ah[4], al[4];
            uint32_t aoff = (uint32_t)(rowA * XLD + kc * 16 + colA) * 2;
            ldmx4(ah, uXH + aoff);
            ldmx4(al, uXL + aoff);
#pragma unroll
            for (int jp = 0; jp < 8; jp++) {
                const int jn = 2 * jp;
                uint32_t bh[4], bl[4];
                uint32_t off = (uint32_t)((8 * jn + rowB4) * XLD + kc * 16 + colB4) * 2;
                ldmx4(bh, uWH + off);
                ldmx4(bl, uWL + off);
                mma_bf16(c[jn],     ah, bh[0], bh[1]);
                mma_bf16(c[jn],     ah, bl[0], bl[1]);
                mma_bf16(c[jn],     al, bh[0], bh[1]);
                mma_bf16(c[jn + 1], ah, bh[2], bh[3]);
                mma_bf16(c[jn + 1], ah, bl[2], bl[3]);
                mma_bf16(c[jn + 1], al, bh[2], bh[3]);
            }
        }
        __syncthreads();
    }

    // epilogue: Q scale folds 1/sqrt(128) AND log2(e) for exp2-domain softmax
    const float sc = (y == 0) ? 0.12753297f : 1.0f;
    __nv_bfloat16* hiA = (y == 0) ? g_qhi : (y == 1) ? g_khi : g_vhi;
    __nv_bfloat16* loA = (y == 0) ? g_qlo : (y == 1) ? g_klo : g_vlo;
    const int grp = lane >> 2;
    const int tic = lane & 3;
    const int r0 = m0 + 16 * w + grp;
    const int r1 = r0 + 8;

#pragma unroll
    for (int jn = 0; jn < 16; jn++) {
        int n = 8 * jn + 2 * tic;
        float2 bo = *(const float2*)(bias + n);
        float o0 = (c[jn][0] + bo.x) * sc;
        float o1 = (c[jn][1] + bo.y) * sc;
        float o2 = (c[jn][2] + bo.x) * sc;
        float o3 = (c[jn][3] + bo.y) * sc;
        uint32_t h0 = packbf2(o0, o1);
        uint32_t h1 = packbf2(o2, o3);
        *(uint32_t*)&hiA[(size_t)r0 * HDIM + n] = h0;
        *(uint32_t*)&hiA[(size_t)r1 * HDIM + n] = h1;
        *(uint32_t*)&loA[(size_t)r0 * HDIM + n] = packbf2(o0 - bflo(h0), o1 - bfhi(h0));
        *(uint32_t*)&loA[(size_t)r1 * HDIM + n] = packbf2(o2 - bflo(h1), o3 - bfhi(h1));
    }
}

// ============================================================================
// FA2-style flash attention (causal), split-bf16 HMMA, 4-way KV split,
// exp2-domain softmax, x4 ldmatrix B-operand loads, deferred cp.async prefetch.
// (R12 core — register-prefetch experiment reverted as neutral.)
// Block (qt, half): kt = half, half+4, ... <= qt.
// ============================================================================
#define LDT 136                         // smem row stride in bf16 (272B)
#define TILE_B (64 * LDT * 2)           // 17408 bytes per tile
#define ASM_QHI 0
#define ASM_QLO (ASM_QHI + TILE_B)
#define ASM_KHI (ASM_QLO + TILE_B)
#define ASM_KLO (ASM_KHI + TILE_B)
#define ASM_VHI (ASM_KLO + TILE_B)
#define ASM_VLO (ASM_VHI + TILE_B)
#define ASM_TOTAL (ASM_VLO + TILE_B)    // 104448 bytes

__global__ __launch_bounds__(128, 2) void attn_kernel()
{
    extern __shared__ char smem[];
    const uint32_t uQHI = smem_u32(smem) + ASM_QHI;
    const uint32_t uQLO = smem_u32(smem) + ASM_QLO;
    const uint32_t uKHI = smem_u32(smem) + ASM_KHI;
    const uint32_t uKLO = smem_u32(smem) + ASM_KLO;
    const uint32_t uVHI = smem_u32(smem) + ASM_VHI;
    const uint32_t uVLO = smem_u32(smem) + ASM_VLO;

    const int tid  = threadIdx.x;
    const int w    = tid >> 5;
    const int lane = tid & 31;
    const int b    = blockIdx.y;
    const int qt   = NQT - 1 - ((int)blockIdx.x >> 2);   // heavy jobs first
    const int half = (int)blockIdx.x & 3;
    const int q0   = qt * 64;

    const int grp  = lane >> 2;
    const int tic  = lane & 3;
    const int rl0  = 16 * w + grp;        // local row within tile
    const int rl1  = rl0 + 8;
    const int qr0  = q0 + rl0;
    const int qr1  = q0 + rl1;

    const size_t job = ((size_t)(b * NQT + qt) * NSPLIT + half);

    // empty job: record identity partial (g_pO slot stays zero-initialized)
    if (half > qt) {
        if (tic == 0) {
            g_pm[job * 64 + rl0] = -1e30f;
            g_pl[job * 64 + rl0] = 0.f;
            g_pm[job * 64 + rl1] = -1e30f;
            g_pl[job * 64 + rl1] = 0.f;
        }
        return;
    }

    const __nv_bfloat16* kh = g_khi + (size_t)b * T_SEQ * HDIM;
    const __nv_bfloat16* kl = g_klo + (size_t)b * T_SEQ * HDIM;
    const __nv_bfloat16* vh = g_vhi + (size_t)b * T_SEQ * HDIM;
    const __nv_bfloat16* vl = g_vlo + (size_t)b * T_SEQ * HDIM;

    auto issueK = [&](int kt_) {
        const int kb = kt_ * 64;
#pragma unroll
        for (int it = 0; it < 8; it++) {
            int idx = tid + it * 128;
            int r = idx >> 4, cc = idx & 15;
            size_t go = (size_t)(kb + r) * HDIM + cc * 8;
            uint32_t so = (uint32_t)(r * LDT + cc * 8) * 2;
            cp16(uKHI + so, kh + go);
            cp16(uKLO + so, kl + go);
        }
        cp_commit();
    };
    auto issueV = [&](int kt_) {
        const int kb = kt_ * 64;
#pragma unroll
        for (int it = 0; it < 8; it++) {
            int idx = tid + it * 128;
            int r = idx >> 4, cc = idx & 15;
            size_t go = (size_t)(kb + r) * HDIM + cc * 8;
            uint32_t so = (uint32_t)(r * LDT + cc * 8) * 2;
            cp16(uVHI + so, vh + go);
            cp16(uVLO + so, vl + go);
        }
        cp_commit();
    };

    float O[16][4];
#pragma unroll
    for (int j = 0; j < 16; j++)
#pragma unroll
        for (int q = 0; q < 4; q++) O[j][q] = 0.f;
    float m0 = -1e30f, m1 = -1e30f, l0 = 0.f, l1 = 0.f;

    const int rowA  = 16 * w + (lane & 15);
    const int colA  = (lane >> 4) * 8;
    const int rowK4 = ((lane >> 4) << 3) + (lane & 7);   // x4 non-trans (j-pair)
    const int colK4 = ((lane >> 3) & 1) * 8;
    const int rowV4 = lane & 15;                         // x4 trans (jn-pair)
    const int colV4 = ((lane >> 4) & 1) * 8;

    // ---- stage Q tile hi/lo into smem (persists) + preload K,V ----
    {
        const __nv_bfloat16* qh = g_qhi + ((size_t)b * T_SEQ + q0) * HDIM;
        const __nv_bfloat16* ql = g_qlo + ((size_t)b * T_SEQ + q0) * HDIM;
#pragma unroll
        for (int it = 0; it < 8; it++) {
            int idx = tid + it * 128;
            int r = idx >> 4, cc = idx & 15;
            uint32_t so = (uint32_t)(r * LDT + cc * 8) * 2;
            cp16(uQHI + so, qh + (size_t)r * HDIM + cc * 8);
            cp16(uQLO + so, ql + (size_t)r * HDIM + cc * 8);
        }
        cp_commit();
    }
    const int kt0 = half;
    issueK(kt0);
    issueV(kt0);
    cp_wait0();
    __syncthreads();

    for (int kt = kt0; kt <= qt; kt += NSPLIT) {
        const bool has_next = (kt + NSPLIT <= qt);
        const int kb = kt * 64;

        // ---- S = Q K^T (split chain, dual accumulators, x4 B loads) ----
        float s_hh[8][4], s_x[8][4];
#pragma unroll
        for (int j = 0; j < 8; j++)
#pragma unroll
            for (int q = 0; q < 4; q++) { s_hh[j][q] = 0.f; s_x[j][q] = 0.f; }

#pragma unroll
        for (int kc = 0; kc < 8; kc++) {
            uint32_t ah[4], al[4];
            uint32_t aoff = (uint32_t)(rowA * LDT + kc * 16 + colA) * 2;
            ldmx4(ah, uQHI + aoff);
            ldmx4(al, uQLO + aoff);
#pragma unroll
            for (int jp = 0; jp < 4; jp++) {
                const int j = 2 * jp;
                uint32_t bh[4], bl[4];
                uint32_t off = (uint32_t)((8 * j + rowK4) * LDT + kc * 16 + colK4) * 2;
                ldmx4(bh, uKHI + off);
                ldmx4(bl, uKLO + off);
                mma_bf16(s_hh[j],     ah, bh[0], bh[1]);
                mma_bf16(s_x[j],      ah, bl[0], bl[1]);
                mma_bf16(s_x[j],      al, bh[0], bh[1]);
                mma_bf16(s_hh[j + 1], ah, bh[2], bh[3]);
                mma_bf16(s_x[j + 1],  ah, bl[2], bl[3]);
                mma_bf16(s_x[j + 1],  al, bh[2], bh[3]);
            }
        }
        __syncthreads();                      // done reading K bufs
        if (has_next) issueK(kt + NSPLIT);    // K prefetch flies during softmax+PV

        // ---- combine + causal mask ----
        float s[8][4];
#pragma unroll
        for (int j = 0; j < 8; j++)
#pragma unroll
            for (int q = 0; q < 4; q++) s[j][q] = s_hh[j][q] + s_x[j][q];
        if (kt == qt) {
            const int cb = kb + 2 * tic;
#pragma unroll
            for (int j = 0; j < 8; j++) {
                int c0 = cb + 8 * j, c1 = c0 + 1;
                if (c0 > qr0) s[j][0] = -1e30f;
                if (c1 > qr0) s[j][1] = -1e30f;
                if (c0 > qr1) s[j][2] = -1e30f;
                if (c1 > qr1) s[j][3] = -1e30f;
            }
        }

        // ---- online softmax (exp2 domain) ----
        float mx0 = -1e30f, mx1 = -1e30f;
#pragma unroll
        for (int j = 0; j < 8; j++) {
            mx0 = fmaxf(mx0, fmaxf(s[j][0], s[j][1]));
            mx1 = fmaxf(mx1, fmaxf(s[j][2], s[j][3]));
        }
        mx0 = fmaxf(mx0, __shfl_xor_sync(0xffffffffu, mx0, 1));
        mx0 = fmaxf(mx0, __shfl_xor_sync(0xffffffffu, mx0, 2));
        mx1 = fmaxf(mx1, __shfl_xor_sync(0xffffffffu, mx1, 1));
        mx1 = fmaxf(mx1, __shfl_xor_sync(0xffffffffu, mx1, 2));
        const float mn0 = fmaxf(m0, mx0);
        const float mn1 = fmaxf(m1, mx1);
        const float al0 = ex2(m0 - mn0);
        const float al1 = ex2(m1 - mn1);
        m0 = mn0; m1 = mn1;

        uint32_t phi[8][2], plo[8][2];
        float la0 = 0.f, la1 = 0.f;
#pragma unroll
        for (int j = 0; j < 8; j++) {
            float p0 = ex2(s[j][0] - mn0);
            float p1 = ex2(s[j][1] - mn0);
            float p2 = ex2(s[j][2] - mn1);
            float p3 = ex2(s[j][3] - mn1);
            la0 += p0 + p1; la1 += p2 + p3;
            uint32_t h0 = packbf2(p0, p1);
            uint32_t h1 = packbf2(p2, p3);
            phi[j][0] = h0; phi[j][1] = h1;
            plo[j][0] = packbf2(p0 - bflo(h0), p1 - bfhi(h0));
            plo[j][1] = packbf2(p2 - bflo(h1), p3 - bfhi(h1));
        }
        la0 += __shfl_xor_sync(0xffffffffu, la0, 1);
        la0 += __shfl_xor_sync(0xffffffffu, la0, 2);
        la1 += __shfl_xor_sync(0xffffffffu, la1, 1);
        la1 += __shfl_xor_sync(0xffffffffu, la1, 2);
        l0 = l0 * al0 + la0;
        l1 = l1 * al1 + la1;

        // skip O rescale when entire warp's alphas are exactly 1
        if (!__all_sync(0xffffffffu, (al0 == 1.f) & (al1 == 1.f))) {
#pragma unroll
            for (int j = 0; j < 16; j++) {
                O[j][0] *= al0; O[j][1] *= al0;
                O[j][2] *= al1; O[j][3] *= al1;
            }
        }

        // V(kt) must be resident: for kt>kt0 its group may still fly
        if (kt > kt0) {
            if (has_next) cp_wait1(); else cp_wait0();
            __syncthreads();
        }

        // ---- O += P V (split chain, x4 trans B loads) ----
#pragma unroll
        for (int kc = 0; kc < 4; kc++) {
            uint32_t ah[4] = { phi[2*kc][0], phi[2*kc][1], phi[2*kc+1][0], phi[2*kc+1][1] };
            uint32_t al[4] = { plo[2*kc][0], plo[2*kc][1], plo[2*kc+1][0], plo[2*kc+1][1] };
            const uint32_t offk = (uint32_t)((16 * kc + rowV4) * LDT + colV4) * 2;
#pragma unroll
            for (int jnp = 0; jnp < 8; jnp++) {
                const int jn = 2 * jnp;
                uint32_t vhf[4], vlf[4];
                uint32_t off = offk + (uint32_t)(8 * jn) * 2;
                ldmx4t(vhf, uVHI + off);
                ldmx4t(vlf, uVLO + off);
                mma_bf16(O[jn],     ah, vhf[0], vhf[1]);
                mma_bf16(O[jn],     ah, vlf[0], vlf[1]);
                mma_bf16(O[jn],     al, vhf[0], vhf[1]);
                mma_bf16(O[jn + 1], ah, vhf[2], vhf[3]);
                mma_bf16(O[jn + 1], ah, vlf[2], vlf[3]);
                mma_bf16(O[jn + 1], al, vhf[2], vhf[3]);
            }
        }
        __syncthreads();                      // done reading V bufs
        if (has_next) {
            issueV(kt + NSPLIT);              // V prefetch flies during next S
            cp_wait1();                       // K(kt+NSPLIT) resident (V still flying)
            __syncthreads();
        }
    }

    // ---- epilogue: write raw partial (O, m, l) ----
    float* pO = g_pO + job * 64 * HDIM;
    if (tic == 0) {
        g_pm[job * 64 + rl0] = m0;
        g_pl[job * 64 + rl0] = l0;
        g_pm[job * 64 + rl1] = m1;
        g_pl[job * 64 + rl1] = l1;
    }
#pragma unroll
    for (int jn = 0; jn < 16; jn++) {
        int col = 8 * jn + 2 * tic;
        *(float2*)(pO + (size_t)rl0 * HDIM + col) = make_float2(O[jn][0], O[jn][1]);
        *(float2*)(pO + (size_t)rl1 * HDIM + col) = make_float2(O[jn][2], O[jn][3]);
    }
}

// ============================================================================
// Merge: combine the NSPLIT KV-split partials per q-row (exp2 domain).
// grid (NQT, BATCH), 256 threads: row = tid>>2 (64 rows), 32 cols/thread.
// ============================================================================
__global__ __launch_bounds__(256) void merge_kernel(float* __restrict__ out)
{
    const int qt = blockIdx.x;
    const int b  = blockIdx.y;
    const int r  = threadIdx.x >> 2;         // 0..63
    const int cq = threadIdx.x & 3;          // col quarter
    const size_t j0 = ((size_t)(b * NQT + qt) * NSPLIT);

    float mM = -1e30f;
    float mv[NSPLIT], lv[NSPLIT];
#pragma unroll
    for (int i = 0; i < NSPLIT; i++) {
        mv[i] = g_pm[(j0 + i) * 64 + r];
        lv[i] = g_pl[(j0 + i) * 64 + r];
        mM = fmaxf(mM, mv[i]);
    }
    float a[NSPLIT], den = 0.f;
#pragma unroll
    for (int i = 0; i < NSPLIT; i++) {
        a[i] = ex2(mv[i] - mM);
        den += a[i] * lv[i];
    }
    const float inv = 1.f / den;

    float* orow = out + ((size_t)b * T_SEQ + qt * 64 + r) * HDIM + cq * 32;
#pragma unroll
    for (int c4 = 0; c4 < 8; c4++) {
        float4 acc = make_float4(0.f, 0.f, 0.f, 0.f);
#pragma unroll
        for (int i = 0; i < NSPLIT; i++) {
            const float* p = g_pO + (j0 + i) * 64 * HDIM + (size_t)r * HDIM + cq * 32 + c4 * 4;
            float4 v = *(const float4*)p;
            acc.x += a[i] * v.x;
            acc.y += a[i] * v.y;
            acc.z += a[i] * v.z;
            acc.w += a[i] * v.w;
        }
        acc.x *= inv; acc.y *= inv; acc.z *= inv; acc.w *= inv;
        *(float4*)(orow + c4 * 4) = acc;
    }
}

// ============================================================================
// launch
// ============================================================================
extern "C" void kernel_launch(void* const* d_in, const int* in_sizes, int n_in,
                              void* d_out, int out_size)
{
    (void)in_sizes; (void)n_in; (void)out_size;
    const float* x  = (const float*)d_in[0];
    // d_in[1] = mask (int32 causal tril) -- causality applied analytically
    const float* wq = (const float*)d_in[2];
    const float* bq = (const float*)d_in[3];
    const float* wk = (const float*)d_in[4];
    const float* bk = (const float*)d_in[5];
    const float* wv = (const float*)d_in[6];
    const float* bv = (const float*)d_in[7];
    float* out = (float*)d_out;

    dim3 gw(DMODEL / 32, HDIM / 32, 3);
    w_split_kernel<<<gw, 256>>>(wq, wk, wv);

    cudaFuncSetAttribute(qkv_hmma_kernel, cudaFuncAttributeMaxDynamicSharedMemorySize, GSM_TOTAL);
    dim3 gg(M_ROWS / 64, 3);
    qkv_hmma_kernel<<<gg, 128, GSM_TOTAL>>>(x, bq, bk, bv);

    cudaFuncSetAttribute(attn_kernel, cudaFuncAttributeMaxDynamicSharedMemorySize, ASM_TOTAL);
    dim3 ga(NSPLIT * NQT, BATCH);
    attn_kernel<<<ga, 128, ASM_TOTAL>>>();

    dim3 gm(NQT, BATCH);
    merge_kernel<<<gm, 256>>>(out);
}

// round 17
// speedup vs baseline: 1.0885x; 1.0369x over previous
#include <cuda_runtime.h>
#include <cuda_bf16.h>
#include <math.h>
#include <stdint.h>

// Problem constants
#define BATCH   4
#define T_SEQ   4096
#define DMODEL  512
#define HDIM    128
#define M_ROWS  (BATCH * T_SEQ)   // 16384
#define NQT     (T_SEQ / 64)      // 64 q-tiles per batch
#define NSPLIT  4                 // KV-split ways
#define NJOBS   (BATCH * NQT * NSPLIT)

// pack two floats to bf16x2 word: lo 16 bits = first arg
__device__ __forceinline__ uint32_t packbf2(float lo, float hi) {
    uint32_t r;
    asm("cvt.rn.satfinite.bf16x2.f32 %0, %1, %2;" : "=r"(r) : "f"(hi), "f"(lo));
    return r;
}
__device__ __forceinline__ float bflo(uint32_t w) { return __uint_as_float(w << 16); }
__device__ __forceinline__ float bfhi(uint32_t w) { return __uint_as_float(w & 0xffff0000u); }
__device__ __forceinline__ float ex2(float x) {
    float y;
    asm("ex2.approx.f32 %0, %1;" : "=f"(y) : "f"(x));
    return y;
}

// ---------------- scratch (device globals: allocation-free) ----------------
__device__ __nv_bfloat16 g_wthi[3 * HDIM * DMODEL];   // W^T [y][n][k]
__device__ __nv_bfloat16 g_wtlo[3 * HDIM * DMODEL];
__device__ __nv_bfloat16 g_qhi[M_ROWS * HDIM];
__device__ __nv_bfloat16 g_qlo[M_ROWS * HDIM];
__device__ __nv_bfloat16 g_khi[M_ROWS * HDIM];
__device__ __nv_bfloat16 g_klo[M_ROWS * HDIM];
__device__ __nv_bfloat16 g_vhi[M_ROWS * HDIM];
__device__ __nv_bfloat16 g_vlo[M_ROWS * HDIM];
// KV-split partials (zero-initialized device globals; empty jobs rely on 0s in g_pO)
__device__ float g_pO[(size_t)NJOBS * 64 * HDIM];     // raw (unnormalized) O
__device__ float g_pm[NJOBS * 64];                    // log2-domain running max
__device__ float g_pl[NJOBS * 64];

// ---------------- mma / ldmatrix / cp.async helpers (base-target ISA) -------
__device__ __forceinline__ uint32_t smem_u32(const void* p) {
    uint32_t a;
    asm("{ .reg .u64 t; cvta.to.shared.u64 t, %1; cvt.u32.u64 %0, t; }" : "=r"(a) : "l"(p));
    return a;
}
__device__ __forceinline__ void mma_bf16(float* c, const uint32_t* a, uint32_t b0, uint32_t b1) {
    asm volatile(
        "mma.sync.aligned.m16n8k16.row.col.f32.bf16.bf16.f32 "
        "{%0,%1,%2,%3},{%4,%5,%6,%7},{%8,%9},{%0,%1,%2,%3};"
        : "+f"(c[0]), "+f"(c[1]), "+f"(c[2]), "+f"(c[3])
        : "r"(a[0]), "r"(a[1]), "r"(a[2]), "r"(a[3]), "r"(b0), "r"(b1));
}
__device__ __forceinline__ void ldmx4(uint32_t* r, uint32_t addr) {
    asm volatile("ldmatrix.sync.aligned.m8n8.x4.shared.b16 {%0,%1,%2,%3}, [%4];"
                 : "=r"(r[0]), "=r"(r[1]), "=r"(r[2]), "=r"(r[3]) : "r"(addr));
}
__device__ __forceinline__ void ldmx4t(uint32_t* r, uint32_t addr) {
    asm volatile("ldmatrix.sync.aligned.m8n8.x4.trans.shared.b16 {%0,%1,%2,%3}, [%4];"
                 : "=r"(r[0]), "=r"(r[1]), "=r"(r[2]), "=r"(r[3]) : "r"(addr));
}
__device__ __forceinline__ void cp16(uint32_t dst, const void* src) {
    asm volatile("cp.async.cg.shared.global [%0], [%1], 16;" :: "r"(dst), "l"(src) : "memory");
}
__device__ __forceinline__ void cp_commit() {
    asm volatile("cp.async.commit_group;" ::: "memory");
}
__device__ __forceinline__ void cp_wait0() {
    asm volatile("cp.async.wait_group 0;" ::: "memory");
}
__device__ __forceinline__ void cp_wait1() {
    asm volatile("cp.async.wait_group 1;" ::: "memory");
}

// ============================================================================
// Prep: transpose + split W [K=512][N=128] -> Wt [N][K] bf16 hi/lo, 3 mats
// ============================================================================
__global__ __launch_bounds__(256) void w_split_kernel(
    const float* __restrict__ wq, const float* __restrict__ wk, const float* __restrict__ wv)
{
    __shared__ float ts[32][33];
    const float* W = (blockIdx.z == 0) ? wq : (blockIdx.z == 1) ? wk : wv;
    const int k0 = blockIdx.x * 32;
    const int n0 = blockIdx.y * 32;
    const int txx = threadIdx.x & 31;
    const int tyy = threadIdx.x >> 5;   // 0..7
#pragma unroll
    for (int r = 0; r < 4; r++)
        ts[tyy + r * 8][txx] = W[(size_t)(k0 + tyy + r * 8) * HDIM + n0 + txx];
    __syncthreads();
#pragma unroll
    for (int r = 0; r < 4; r++) {
        int n = n0 + tyy + r * 8;
        int k = k0 + txx;
        float v = ts[txx][tyy + r * 8];
        __nv_bfloat16 hb = __float2bfloat16(v);
        float rr = v - __bfloat162float(hb);
        size_t o = (size_t)blockIdx.z * HDIM * DMODEL + (size_t)n * DMODEL + k;
        g_wthi[o] = hb;
        g_wtlo[o] = __float2bfloat16(rr);
    }
}

// ============================================================================
// QKV projection GEMM via HMMA split-bf16, 2-stage double buffer.
// X loaded fp32 via LDG one chunk ahead, split to bf16 hi/lo in-register,
// STS'd into the staging buffers (split_x kernel fused away).
// BM=64, N=128 full, K=512 in chunks of 64; 128 thr (4 warps, 16 rows/warp).
// ============================================================================
#define XLD 72                                // smem row stride (bf16)
#define GX_B   (64  * XLD * 2)                //  9216 B per X tile
#define GW_B   (128 * XLD * 2)                // 18432 B per W tile
#define GSM_XH 0
#define GSM_XL (GSM_XH + GX_B)
#define GSM_WH (GSM_XL + GX_B)
#define GSM_WL (GSM_WH + GW_B)
#define GSTG   (GSM_WL + GW_B)                // 55296 B per stage
#define GSM_TOTAL (2 * GSTG)                  // 110592 B
#define NCHUNK (DMODEL / 64)                  // 8

__global__ __launch_bounds__(128, 2) void qkv_hmma_kernel(
    const float* __restrict__ x,
    const float* __restrict__ bq, const float* __restrict__ bk, const float* __restrict__ bv)
{
    extern __shared__ char sg[];
    const uint32_t base = smem_u32(sg);

    const int tid  = threadIdx.x;
    const int w    = tid >> 5;
    const int lane = tid & 31;
    const int m0   = blockIdx.x * 64;
    const int y    = blockIdx.y;

    const __nv_bfloat16* wth = g_wthi + (size_t)y * HDIM * DMODEL;
    const __nv_bfloat16* wtl = g_wtlo + (size_t)y * HDIM * DMODEL;
    const float* bias = (y == 0) ? bq : (y == 1) ? bk : bv;

    float c[16][4];
#pragma unroll
    for (int j = 0; j < 16; j++)
#pragma unroll
        for (int q = 0; q < 4; q++) c[j][q] = 0.f;

    const int rowA  = 16 * w + (lane & 15);
    const int colA  = (lane >> 4) * 8;
    const int rowB4 = ((lane >> 4) << 3) + (lane & 7);   // x4: row within jn-pair
    const int colB4 = ((lane >> 3) & 1) * 8;

    float4 xr[8];

    auto ldgX = [&](int cidx) {
        const int k0 = cidx * 64;
#pragma unroll
        for (int it = 0; it < 8; it++) {
            int idx = tid + it * 128;
            int r = idx >> 4, c4 = idx & 15;
            xr[it] = *(const float4*)(x + (size_t)(m0 + r) * DMODEL + k0 + c4 * 4);
        }
    };
    auto stsX = [&](int stage) {
#pragma unroll
        for (int it = 0; it < 8; it++) {
            int idx = tid + it * 128;
            int r = idx >> 4, c4 = idx & 15;
            float4 v = xr[it];
            uint32_t h0 = packbf2(v.x, v.y);
            uint32_t h1 = packbf2(v.z, v.w);
            uint32_t l0 = packbf2(v.x - bflo(h0), v.y - bfhi(h0));
            uint32_t l1 = packbf2(v.z - bflo(h1), v.w - bfhi(h1));
            uint32_t so = (uint32_t)(r * XLD + c4 * 4) * 2;
            *(uint2*)(sg + (stage * GSTG + GSM_XH) + so) = make_uint2(h0, h1);
            *(uint2*)(sg + (stage * GSTG + GSM_XL) + so) = make_uint2(l0, l1);
        }
    };
    auto issueW = [&](int cidx, int stage) {
        const int k0 = cidx * 64;
        const uint32_t uWH = base + stage * GSTG + GSM_WH;
        const uint32_t uWL = base + stage * GSTG + GSM_WL;
#pragma unroll
        for (int it = 0; it < 8; it++) {
            int idx = tid + it * 128;
            int r = idx >> 3, cc = idx & 7;
            size_t go = (size_t)r * DMODEL + k0 + cc * 8;
            uint32_t so = (uint32_t)(r * XLD + cc * 8) * 2;
            cp16(uWH + so, wth + go);
            cp16(uWL + so, wtl + go);
        }
        cp_commit();
    };

    // prologue: W(0) via cp.async, X(0) via LDG
    issueW(0, 0);
    ldgX(0);

    for (int cidx = 0; cidx < NCHUNK; cidx++) {
        const int stage = cidx & 1;
        const bool has_next = (cidx + 1 < NCHUNK);
        if (has_next) issueW(cidx + 1, stage ^ 1);
        stsX(stage);                       // convert + store current X chunk
        if (has_next) ldgX(cidx + 1);      // prefetch next X into regs
        if (has_next) cp_wait1(); else cp_wait0();   // W(cidx) resident
        __syncthreads();

        const uint32_t uXH = base + stage * GSTG + GSM_XH;
        const uint32_t uXL = base + stage * GSTG + GSM_XL;
        const uint32_t uWH = base + stage * GSTG + GSM_WH;
        const uint32_t uWL = base + stage * GSTG + GSM_WL;
#pragma unroll
        for (int kc = 0; kc < 4; kc++) {
            uint32_t ah[4], al[4];
            uint32_t aoff = (uint32_t)(rowA * XLD + kc * 16 + colA) * 2;
            ldmx4(ah, uXH + aoff);
            ldmx4(al, uXL + aoff);
#pragma unroll
            for (int jp = 0; jp < 8; jp++) {
                const int jn = 2 * jp;
                uint32_t bh[4], bl[4];
                uint32_t off = (uint32_t)((8 * jn + rowB4) * XLD + kc * 16 + colB4) * 2;
                ldmx4(bh, uWH + off);
                ldmx4(bl, uWL + off);
                mma_bf16(c[jn],     ah, bh[0], bh[1]);
                mma_bf16(c[jn],     ah, bl[0], bl[1]);
                mma_bf16(c[jn],     al, bh[0], bh[1]);
                mma_bf16(c[jn + 1], ah, bh[2], bh[3]);
                mma_bf16(c[jn + 1], ah, bl[2], bl[3]);
                mma_bf16(c[jn + 1], al, bh[2], bh[3]);
            }
        }
        __syncthreads();
    }

    // epilogue: Q scale folds 1/sqrt(128) AND log2(e) for exp2-domain softmax
    const float sc = (y == 0) ? 0.12753297f : 1.0f;
    __nv_bfloat16* hiA = (y == 0) ? g_qhi : (y == 1) ? g_khi : g_vhi;
    __nv_bfloat16* loA = (y == 0) ? g_qlo : (y == 1) ? g_klo : g_vlo;
    const int grp = lane >> 2;
    const int tic = lane & 3;
    const int r0 = m0 + 16 * w + grp;
    const int r1 = r0 + 8;

#pragma unroll
    for (int jn = 0; jn < 16; jn++) {
        int n = 8 * jn + 2 * tic;
        float2 bo = *(const float2*)(bias + n);
        float o0 = (c[jn][0] + bo.x) * sc;
        float o1 = (c[jn][1] + bo.y) * sc;
        float o2 = (c[jn][2] + bo.x) * sc;
        float o3 = (c[jn][3] + bo.y) * sc;
        uint32_t h0 = packbf2(o0, o1);
        uint32_t h1 = packbf2(o2, o3);
        *(uint32_t*)&hiA[(size_t)r0 * HDIM + n] = h0;
        *(uint32_t*)&hiA[(size_t)r1 * HDIM + n] = h1;
        *(uint32_t*)&loA[(size_t)r0 * HDIM + n] = packbf2(o0 - bflo(h0), o1 - bfhi(h0));
        *(uint32_t*)&loA[(size_t)r1 * HDIM + n] = packbf2(o2 - bflo(h1), o3 - bfhi(h1));
    }
}

// ============================================================================
// FA2-style flash attention (causal), split-bf16 HMMA, 4-way KV split,
// exp2-domain softmax, x4 ldmatrix B-operand loads, deferred cp.async prefetch.
// Block (qt, half): kt = half, half+4, ... <= qt.
// ============================================================================
#define LDT 136                         // smem row stride in bf16 (272B)
#define TILE_B (64 * LDT * 2)           // 17408 bytes per tile
#define ASM_QHI 0
#define ASM_QLO (ASM_QHI + TILE_B)
#define ASM_KHI (ASM_QLO + TILE_B)
#define ASM_KLO (ASM_KHI + TILE_B)
#define ASM_VHI (ASM_KLO + TILE_B)
#define ASM_VLO (ASM_VHI + TILE_B)
#define ASM_TOTAL (ASM_VLO + TILE_B)    // 104448 bytes

__global__ __launch_bounds__(128, 2) void attn_kernel()
{
    extern __shared__ char smem[];
    const uint32_t uQHI = smem_u32(smem) + ASM_QHI;
    const uint32_t uQLO = smem_u32(smem) + ASM_QLO;
    const uint32_t uKHI = smem_u32(smem) + ASM_KHI;
    const uint32_t uKLO = smem_u32(smem) + ASM_KLO;
    const uint32_t uVHI = smem_u32(smem) + ASM_VHI;
    const uint32_t uVLO = smem_u32(smem) + ASM_VLO;

    const int tid  = threadIdx.x;
    const int w    = tid >> 5;
    const int lane = tid & 31;
    const int b    = blockIdx.y;
    const int qt   = NQT - 1 - ((int)blockIdx.x >> 2);   // heavy jobs first
    const int half = (int)blockIdx.x & 3;
    const int q0   = qt * 64;

    const int grp  = lane >> 2;
    const int tic  = lane & 3;
    const int rl0  = 16 * w + grp;        // local row within tile
    const int rl1  = rl0 + 8;
    const int qr0  = q0 + rl0;
    const int qr1  = q0 + rl1;

    const size_t job = ((size_t)(b * NQT + qt) * NSPLIT + half);

    // empty job: record identity partial (g_pO slot stays zero-initialized)
    if (half > qt) {
        if (tic == 0) {
            g_pm[job * 64 + rl0] = -1e30f;
            g_pl[job * 64 + rl0] = 0.f;
            g_pm[job * 64 + rl1] = -1e30f;
            g_pl[job * 64 + rl1] = 0.f;
        }
        return;
    }

    const __nv_bfloat16* kh = g_khi + (size_t)b * T_SEQ * HDIM;
    const __nv_bfloat16* kl = g_klo + (size_t)b * T_SEQ * HDIM;
    const __nv_bfloat16* vh = g_vhi + (size_t)b * T_SEQ * HDIM;
    const __nv_bfloat16* vl = g_vlo + (size_t)b * T_SEQ * HDIM;

    auto issueK = [&](int kt_) {
        const int kb = kt_ * 64;
#pragma unroll
        for (int it = 0; it < 8; it++) {
            int idx = tid + it * 128;
            int r = idx >> 4, cc = idx & 15;
            size_t go = (size_t)(kb + r) * HDIM + cc * 8;
            uint32_t so = (uint32_t)(r * LDT + cc * 8) * 2;
            cp16(uKHI + so, kh + go);
            cp16(uKLO + so, kl + go);
        }
        cp_commit();
    };
    auto issueV = [&](int kt_) {
        const int kb = kt_ * 64;
#pragma unroll
        for (int it = 0; it < 8; it++) {
            int idx = tid + it * 128;
            int r = idx >> 4, cc = idx & 15;
            size_t go = (size_t)(kb + r) * HDIM + cc * 8;
            uint32_t so = (uint32_t)(r * LDT + cc * 8) * 2;
            cp16(uVHI + so, vh + go);
            cp16(uVLO + so, vl + go);
        }
        cp_commit();
    };

    float O[16][4];
#pragma unroll
    for (int j = 0; j < 16; j++)
#pragma unroll
        for (int q = 0; q < 4; q++) O[j][q] = 0.f;
    float m0 = -1e30f, m1 = -1e30f, l0 = 0.f, l1 = 0.f;

    const int rowA  = 16 * w + (lane & 15);
    const int colA  = (lane >> 4) * 8;
    const int rowK4 = ((lane >> 4) << 3) + (lane & 7);   // x4 non-trans (j-pair)
    const int colK4 = ((lane >> 3) & 1) * 8;
    const int rowV4 = lane & 15;                         // x4 trans (jn-pair)
    const int colV4 = ((lane >> 4) & 1) * 8;

    // ---- stage Q tile hi/lo into smem (persists) + preload K,V ----
    {
        const __nv_bfloat16* qh = g_qhi + ((size_t)b * T_SEQ + q0) * HDIM;
        const __nv_bfloat16* ql = g_qlo + ((size_t)b * T_SEQ + q0) * HDIM;
#pragma unroll
        for (int it = 0; it < 8; it++) {
            int idx = tid + it * 128;
            int r = idx >> 4, cc = idx & 15;
            uint32_t so = (uint32_t)(r * LDT + cc * 8) * 2;
            cp16(uQHI + so, qh + (size_t)r * HDIM + cc * 8);
            cp16(uQLO + so, ql + (size_t)r * HDIM + cc * 8);
        }
        cp_commit();
    }
    const int kt0 = half;
    issueK(kt0);
    issueV(kt0);
    cp_wait0();
    __syncthreads();

    for (int kt = kt0; kt <= qt; kt += NSPLIT) {
        const bool has_next = (kt + NSPLIT <= qt);
        const int kb = kt * 64;

        // ---- S = Q K^T (split chain, dual accumulators, x4 B loads) ----
        float s_hh[8][4], s_x[8][4];
#pragma unroll
        for (int j = 0; j < 8; j++)
#pragma unroll
            for (int q = 0; q < 4; q++) { s_hh[j][q] = 0.f; s_x[j][q] = 0.f; }

#pragma unroll
        for (int kc = 0; kc < 8; kc++) {
            uint32_t ah[4], al[4];
            uint32_t aoff = (uint32_t)(rowA * LDT + kc * 16 + colA) * 2;
            ldmx4(ah, uQHI + aoff);
            ldmx4(al, uQLO + aoff);
#pragma unroll
            for (int jp = 0; jp < 4; jp++) {
                const int j = 2 * jp;
                uint32_t bh[4], bl[4];
                uint32_t off = (uint32_t)((8 * j + rowK4) * LDT + kc * 16 + colK4) * 2;
                ldmx4(bh, uKHI + off);
                ldmx4(bl, uKLO + off);
                mma_bf16(s_hh[j],     ah, bh[0], bh[1]);
                mma_bf16(s_x[j],      ah, bl[0], bl[1]);
                mma_bf16(s_x[j],      al, bh[0], bh[1]);
                mma_bf16(s_hh[j + 1], ah, bh[2], bh[3]);
                mma_bf16(s_x[j + 1],  ah, bl[2], bl[3]);
                mma_bf16(s_x[j + 1],  al, bh[2], bh[3]);
            }
        }
        __syncthreads();                      // done reading K bufs
        if (has_next) issueK(kt + NSPLIT);    // K prefetch flies during softmax+PV

        // ---- combine + causal mask ----
        float s[8][4];
#pragma unroll
        for (int j = 0; j < 8; j++)
#pragma unroll
            for (int q = 0; q < 4; q++) s[j][q] = s_hh[j][q] + s_x[j][q];
        if (kt == qt) {
            const int cb = kb + 2 * tic;
#pragma unroll
            for (int j = 0; j < 8; j++) {
                int c0 = cb + 8 * j, c1 = c0 + 1;
                if (c0 > qr0) s[j][0] = -1e30f;
                if (c1 > qr0) s[j][1] = -1e30f;
                if (c0 > qr1) s[j][2] = -1e30f;
                if (c1 > qr1) s[j][3] = -1e30f;
            }
        }

        // ---- online softmax (exp2 domain) ----
        float mx0 = -1e30f, mx1 = -1e30f;
#pragma unroll
        for (int j = 0; j < 8; j++) {
            mx0 = fmaxf(mx0, fmaxf(s[j][0], s[j][1]));
            mx1 = fmaxf(mx1, fmaxf(s[j][2], s[j][3]));
        }
        mx0 = fmaxf(mx0, __shfl_xor_sync(0xffffffffu, mx0, 1));
        mx0 = fmaxf(mx0, __shfl_xor_sync(0xffffffffu, mx0, 2));
        mx1 = fmaxf(mx1, __shfl_xor_sync(0xffffffffu, mx1, 1));
        mx1 = fmaxf(mx1, __shfl_xor_sync(0xffffffffu, mx1, 2));
        const float mn0 = fmaxf(m0, mx0);
        const float mn1 = fmaxf(m1, mx1);
        const float al0 = ex2(m0 - mn0);
        const float al1 = ex2(m1 - mn1);
        m0 = mn0; m1 = mn1;

        uint32_t phi[8][2], plo[8][2];
        float la0 = 0.f, la1 = 0.f;
#pragma unroll
        for (int j = 0; j < 8; j++) {
            float p0 = ex2(s[j][0] - mn0);
            float p1 = ex2(s[j][1] - mn0);
            float p2 = ex2(s[j][2] - mn1);
            float p3 = ex2(s[j][3] - mn1);
            la0 += p0 + p1; la1 += p2 + p3;
            uint32_t h0 = packbf2(p0, p1);
            uint32_t h1 = packbf2(p2, p3);
            phi[j][0] = h0; phi[j][1] = h1;
            plo[j][0] = packbf2(p0 - bflo(h0), p1 - bfhi(h0));
            plo[j][1] = packbf2(p2 - bflo(h1), p3 - bfhi(h1));
        }
        la0 += __shfl_xor_sync(0xffffffffu, la0, 1);
        la0 += __shfl_xor_sync(0xffffffffu, la0, 2);
        la1 += __shfl_xor_sync(0xffffffffu, la1, 1);
        la1 += __shfl_xor_sync(0xffffffffu, la1, 2);
        l0 = l0 * al0 + la0;
        l1 = l1 * al1 + la1;

        // skip O rescale when entire warp's alphas are exactly 1
        if (!__all_sync(0xffffffffu, (al0 == 1.f) & (al1 == 1.f))) {
#pragma unroll
            for (int j = 0; j < 16; j++) {
                O[j][0] *= al0; O[j][1] *= al0;
                O[j][2] *= al1; O[j][3] *= al1;
            }
        }

        // V(kt) must be resident: for kt>kt0 its group may still fly
        if (kt > kt0) {
            if (has_next) cp_wait1(); else cp_wait0();
            __syncthreads();
        }

        // ---- O += P V (split chain, x4 trans B loads) ----
#pragma unroll
        for (int kc = 0; kc < 4; kc++) {
            uint32_t ah[4] = { phi[2*kc][0], phi[2*kc][1], phi[2*kc+1][0], phi[2*kc+1][1] };
            uint32_t al[4] = { plo[2*kc][0], plo[2*kc][1], plo[2*kc+1][0], plo[2*kc+1][1] };
            const uint32_t offk = (uint32_t)((16 * kc + rowV4) * LDT + colV4) * 2;
#pragma unroll
            for (int jnp = 0; jnp < 8; jnp++) {
                const int jn = 2 * jnp;
                uint32_t vhf[4], vlf[4];
                uint32_t off = offk + (uint32_t)(8 * jn) * 2;
                ldmx4t(vhf, uVHI + off);
                ldmx4t(vlf, uVLO + off);
                mma_bf16(O[jn],     ah, vhf[0], vhf[1]);
                mma_bf16(O[jn],     ah, vlf[0], vlf[1]);
                mma_bf16(O[jn],     al, vhf[0], vhf[1]);
                mma_bf16(O[jn + 1], ah, vhf[2], vhf[3]);
                mma_bf16(O[jn + 1], ah, vlf[2], vlf[3]);
                mma_bf16(O[jn + 1], al, vhf[2], vhf[3]);
            }
        }
        __syncthreads();                      // done reading V bufs
        if (has_next) {
            issueV(kt + NSPLIT);              // V prefetch flies during next S
            cp_wait1();                       // K(kt+NSPLIT) resident (V still flying)
            __syncthreads();
        }
    }

    // ---- epilogue: write raw partial (O, m, l) ----
    float* pO = g_pO + job * 64 * HDIM;
    if (tic == 0) {
        g_pm[job * 64 + rl0] = m0;
        g_pl[job * 64 + rl0] = l0;
        g_pm[job * 64 + rl1] = m1;
        g_pl[job * 64 + rl1] = l1;
    }
#pragma unroll
    for (int jn = 0; jn < 16; jn++) {
        int col = 8 * jn + 2 * tic;
        *(float2*)(pO + (size_t)rl0 * HDIM + col) = make_float2(O[jn][0], O[jn][1]);
        *(float2*)(pO + (size_t)rl1 * HDIM + col) = make_float2(O[jn][2], O[jn][3]);
    }
}

// ============================================================================
// Merge v2: combine the NSPLIT KV-split partials per q-row (exp2 domain).
// 4x parallelism vs v1: grid (NQT*4, BATCH); block = 16 rows; 256 threads;
// thread = (row, col-16th): 8 columns = 2 float4 per split.
// ============================================================================
__global__ __launch_bounds__(256) void merge_kernel(float* __restrict__ out)
{
    const int qt  = blockIdx.x >> 2;
    const int sub = blockIdx.x & 3;          // 16-row group
    const int b   = blockIdx.y;
    const int r   = sub * 16 + (threadIdx.x >> 4);   // 0..63
    const int cg  = threadIdx.x & 15;                // 8 cols each
    const size_t j0 = ((size_t)(b * NQT + qt) * NSPLIT);

    float mM = -1e30f;
    float mv[NSPLIT], lv[NSPLIT];
#pragma unroll
    for (int i = 0; i < NSPLIT; i++) {
        mv[i] = g_pm[(j0 + i) * 64 + r];
        lv[i] = g_pl[(j0 + i) * 64 + r];
        mM = fmaxf(mM, mv[i]);
    }
    float a[NSPLIT], den = 0.f;
#pragma unroll
    for (int i = 0; i < NSPLIT; i++) {
        a[i] = ex2(mv[i] - mM);
        den += a[i] * lv[i];
    }
    const float inv = 1.f / den;

    // gather all 8 loads up-front (max MLP), then combine
    float4 v0[NSPLIT], v1[NSPLIT];
#pragma unroll
    for (int i = 0; i < NSPLIT; i++) {
        const float* p = g_pO + (j0 + i) * 64 * HDIM + (size_t)r * HDIM + cg * 8;
        v0[i] = *(const float4*)(p);
        v1[i] = *(const float4*)(p + 4);
    }
    float4 o0 = make_float4(0.f, 0.f, 0.f, 0.f);
    float4 o1 = make_float4(0.f, 0.f, 0.f, 0.f);
#pragma unroll
    for (int i = 0; i < NSPLIT; i++) {
        o0.x += a[i] * v0[i].x; o0.y += a[i] * v0[i].y;
        o0.z += a[i] * v0[i].z; o0.w += a[i] * v0[i].w;
        o1.x += a[i] * v1[i].x; o1.y += a[i] * v1[i].y;
        o1.z += a[i] * v1[i].z; o1.w += a[i] * v1[i].w;
    }
    o0.x *= inv; o0.y *= inv; o0.z *= inv; o0.w *= inv;
    o1.x *= inv; o1.y *= inv; o1.z *= inv; o1.w *= inv;

    float* orow = out + ((size_t)b * T_SEQ + qt * 64 + r) * HDIM + cg * 8;
    *(float4*)(orow)     = o0;
    *(float4*)(orow + 4) = o1;
}

// ============================================================================
// launch
// ============================================================================
extern "C" void kernel_launch(void* const* d_in, const int* in_sizes, int n_in,
                              void* d_out, int out_size)
{
    (void)in_sizes; (void)n_in; (void)out_size;
    const float* x  = (const float*)d_in[0];
    // d_in[1] = mask (int32 causal tril) -- causality applied analytically
    const float* wq = (const float*)d_in[2];
    const float* bq = (const float*)d_in[3];
    const float* wk = (const float*)d_in[4];
    const float* bk = (const float*)d_in[5];
    const float* wv = (const float*)d_in[6];
    const float* bv = (const float*)d_in[7];
    float* out = (float*)d_out;

    dim3 gw(DMODEL / 32, HDIM / 32, 3);
    w_split_kernel<<<gw, 256>>>(wq, wk, wv);

    cudaFuncSetAttribute(qkv_hmma_kernel, cudaFuncAttributeMaxDynamicSharedMemorySize, GSM_TOTAL);
    dim3 gg(M_ROWS / 64, 3);
    qkv_hmma_kernel<<<gg, 128, GSM_TOTAL>>>(x, bq, bk, bv);

    cudaFuncSetAttribute(attn_kernel, cudaFuncAttributeMaxDynamicSharedMemorySize, ASM_TOTAL);
    dim3 ga(NSPLIT * NQT, BATCH);
    attn_kernel<<<ga, 128, ASM_TOTAL>>>();

    dim3 gm(NQT * 4, BATCH);
    merge_kernel<<<gm, 256>>>(out);
}